// round 1
// baseline (speedup 1.0000x reference)
#include <cuda_runtime.h>

// Problem constants
#define TT    4096
#define EMB   1024
#define H2    512
#define G4    2048       // 4 * H2
#define NTAGS 5
#define START 3
#define STOP  4
#define NEGV  -10000.0f

// Recurrence parallelization
#define NCTA  64         // CTAs per direction
#define HPER  8          // hidden units per CTA  (NCTA * HPER = H2)

// -------------------- scratch (static device globals; no allocs) ------------
__device__ float d_xs[TT * EMB];          // embedded inputs        (16 MB)
__device__ float d_G[2][TT * G4];         // precomputed input gates (64 MB)
__device__ float d_h[2][TT * H2];         // hidden states per step (16 MB)
__device__ float d_feats[TT * NTAGS];     // tag scores
__device__ int   d_cnt[2][TT];            // per-step arrival counters

// -------------------- helpers ----------------------------------------------
__device__ __forceinline__ int ld_acquire_gpu(const int* p) {
    int v;
    asm volatile("ld.acquire.gpu.b32 %0, [%1];" : "=r"(v) : "l"(p) : "memory");
    return v;
}

__device__ __forceinline__ float sigmoidf(float x) {
    return 1.0f / (1.0f + expf(-x));
}

// -------------------- kernel: zero counters ---------------------------------
__global__ void k_zero() {
    int i = blockIdx.x * blockDim.x + threadIdx.x;
    if (i < 2 * TT) d_cnt[i / TT][i % TT] = 0;
}

// -------------------- kernel: embedding gather ------------------------------
__global__ void k_gather(const int* __restrict__ sent,
                         const float* __restrict__ embed) {
    int t = blockIdx.x;
    int row = sent[t];
    const float4* src = (const float4*)(embed + (size_t)row * EMB);
    float4* dst = (float4*)(d_xs + (size_t)t * EMB);
    dst[threadIdx.x] = src[threadIdx.x];   // 256 threads * float4 = 1024 floats
}

// -------------------- kernel: input GEMM  G = xs @ Wih^T + (bih+bhh) --------
// C tile 128x128, K tile 16, 256 threads, 8x8 register blocking.
// dir==1 consumes xs in reversed time order (backward LSTM).
__global__ __launch_bounds__(256) void k_gemm(
    const float* __restrict__ Wf, const float* __restrict__ Wb,
    const float* __restrict__ bihf, const float* __restrict__ bhhf,
    const float* __restrict__ bihb, const float* __restrict__ bhhb) {
    int dir = blockIdx.z;
    const float* W  = dir ? Wb   : Wf;
    const float* b1 = dir ? bihb : bihf;
    const float* b2 = dir ? bhhb : bhhf;
    float* Gp = d_G[dir];

    __shared__ float As[16 * 128];
    __shared__ float Bs[16 * 128];

    int tid = threadIdx.x;
    int m0 = blockIdx.y * 128;
    int n0 = blockIdx.x * 128;
    int ty = tid >> 4, tx = tid & 15;

    float acc[8][8];
#pragma unroll
    for (int i = 0; i < 8; i++)
#pragma unroll
        for (int j = 0; j < 8; j++) acc[i][j] = 0.0f;

    for (int k0 = 0; k0 < EMB; k0 += 16) {
#pragma unroll
        for (int h = 0; h < 2; h++) {
            int f = tid + h * 256;          // 512 float4 slots
            int row = f >> 2, kq = f & 3;
            int srcRow = m0 + row;
            if (dir) srcRow = TT - 1 - srcRow;
            float4 va = *(const float4*)(d_xs + (size_t)srcRow * EMB + k0 + kq * 4);
            As[(kq * 4 + 0) * 128 + row] = va.x;
            As[(kq * 4 + 1) * 128 + row] = va.y;
            As[(kq * 4 + 2) * 128 + row] = va.z;
            As[(kq * 4 + 3) * 128 + row] = va.w;
            float4 vb = *(const float4*)(W + (size_t)(n0 + row) * EMB + k0 + kq * 4);
            Bs[(kq * 4 + 0) * 128 + row] = vb.x;
            Bs[(kq * 4 + 1) * 128 + row] = vb.y;
            Bs[(kq * 4 + 2) * 128 + row] = vb.z;
            Bs[(kq * 4 + 3) * 128 + row] = vb.w;
        }
        __syncthreads();
#pragma unroll
        for (int k = 0; k < 16; k++) {
            float a[8], bb[8];
#pragma unroll
            for (int i = 0; i < 8; i++) a[i]  = As[k * 128 + ty * 8 + i];
#pragma unroll
            for (int j = 0; j < 8; j++) bb[j] = Bs[k * 128 + tx * 8 + j];
#pragma unroll
            for (int i = 0; i < 8; i++)
#pragma unroll
                for (int j = 0; j < 8; j++) acc[i][j] += a[i] * bb[j];
        }
        __syncthreads();
    }

    float bias[8];
#pragma unroll
    for (int j = 0; j < 8; j++) {
        int n = n0 + tx * 8 + j;
        bias[j] = b1[n] + b2[n];
    }
#pragma unroll
    for (int i = 0; i < 8; i++) {
        int m = m0 + ty * 8 + i;
#pragma unroll
        for (int j = 0; j < 8; j++) {
            int n = n0 + tx * 8 + j;
            Gp[(size_t)m * G4 + n] = acc[i][j] + bias[j];
        }
    }
}

// -------------------- kernel: persistent LSTM recurrence --------------------
// grid = 2*NCTA CTAs, 512 threads each. CTA (dir, slice) owns hidden units
// [slice*HPER, slice*HPER+HPER) of direction dir: 4 gates * HPER = 32 rows of
// Whh, cached in registers (32 floats/thread). Per step: read full h (512 f32),
// slice GEMV, update its h slice, arrive on an L2 counter, spin for the rest.
__global__ void __launch_bounds__(512, 1) k_recur(
    const float* __restrict__ Whh_f, const float* __restrict__ Whh_b,
    const float* __restrict__ h0, const float* __restrict__ c0) {
    int dir   = blockIdx.x / NCTA;
    int slice = blockIdx.x % NCTA;
    int hbase = slice * HPER;
    const float* Whh = dir ? Whh_b : Whh_f;
    const float* Gd = d_G[dir];
    float* hout = d_h[dir];
    int* cnt = d_cnt[dir];

    int tid = threadIdx.x;
    int warp = tid >> 5, lane = tid & 31;

    // Load this thread's weight slice: 2 rows x 16 k-values
    float w[2][16];
#pragma unroll
    for (int i = 0; i < 2; i++) {
        int r = warp * 2 + i;            // 0..31
        int g = r >> 3, j = r & 7;
        int row = g * H2 + hbase + j;
        const float4* Wr = (const float4*)(Whh + (size_t)row * H2 + lane * 16);
        float4 v0 = Wr[0], v1 = Wr[1], v2 = Wr[2], v3 = Wr[3];
        w[i][0]=v0.x; w[i][1]=v0.y; w[i][2]=v0.z; w[i][3]=v0.w;
        w[i][4]=v1.x; w[i][5]=v1.y; w[i][6]=v1.z; w[i][7]=v1.w;
        w[i][8]=v2.x; w[i][9]=v2.y; w[i][10]=v2.z; w[i][11]=v2.w;
        w[i][12]=v3.x; w[i][13]=v3.y; w[i][14]=v3.z; w[i][15]=v3.w;
    }

    __shared__ float sh[H2];
    __shared__ float gate_s[32];

    float cj = 0.0f;
    if (tid < HPER) cj = c0[dir * H2 + hbase + tid];

    for (int t = 0; t < TT; t++) {
        const float* hp = (t == 0) ? (h0 + dir * H2)
                                   : (hout + (size_t)(t - 1) * H2);
        sh[tid] = hp[tid];
        float gv[4];
        if (tid < HPER) {
#pragma unroll
            for (int g = 0; g < 4; g++)
                gv[g] = Gd[(size_t)t * G4 + g * H2 + hbase + tid];
        }
        __syncthreads();

        float acc0 = 0.0f, acc1 = 0.0f;
        const float4* sh4 = (const float4*)sh;
#pragma unroll
        for (int q = 0; q < 4; q++) {
            float4 hv = sh4[lane * 4 + q];
            acc0 += w[0][q*4+0]*hv.x + w[0][q*4+1]*hv.y + w[0][q*4+2]*hv.z + w[0][q*4+3]*hv.w;
            acc1 += w[1][q*4+0]*hv.x + w[1][q*4+1]*hv.y + w[1][q*4+2]*hv.z + w[1][q*4+3]*hv.w;
        }
#pragma unroll
        for (int off = 16; off > 0; off >>= 1) {
            acc0 += __shfl_xor_sync(0xffffffffu, acc0, off);
            acc1 += __shfl_xor_sync(0xffffffffu, acc1, off);
        }
        if (lane == 0) {
            gate_s[warp * 2 + 0] = acc0;
            gate_s[warp * 2 + 1] = acc1;
        }
        __syncthreads();

        if (tid < HPER) {
            int j = tid;
            float gi = gate_s[0 * HPER + j] + gv[0];
            float gf = gate_s[1 * HPER + j] + gv[1];
            float gg = gate_s[2 * HPER + j] + gv[2];
            float go = gate_s[3 * HPER + j] + gv[3];
            cj = sigmoidf(gf) * cj + sigmoidf(gi) * tanhf(gg);
            float hj = sigmoidf(go) * tanhf(cj);
            hout[(size_t)t * H2 + hbase + j] = hj;
            __threadfence();               // make my h write GPU-visible
        }
        __syncwarp();
        if (tid == 0) {
            atomicAdd(&cnt[t], 1);
            while (ld_acquire_gpu(&cnt[t]) < NCTA) { __nanosleep(32); }
        }
        __syncthreads();
    }
}

// -------------------- kernel: output projection feats = [hf|hb] @ Wout^T ----
__global__ void k_feats(const float* __restrict__ Wout,
                        const float* __restrict__ bout) {
    int t = blockIdx.x;
    int n = threadIdx.x >> 5;              // 5 warps -> 5 tags
    int lane = threadIdx.x & 31;
    const float* hf = d_h[0] + (size_t)t * H2;
    const float* hb = d_h[1] + (size_t)(TT - 1 - t) * H2;  // backward state at time t
    float s = 0.0f;
    const float* Wn = Wout + (size_t)n * (2 * H2);
#pragma unroll 4
    for (int k = lane; k < H2; k += 32) s += Wn[k] * hf[k];
#pragma unroll 4
    for (int k = lane; k < H2; k += 32) s += Wn[H2 + k] * hb[k];
#pragma unroll
    for (int off = 16; off > 0; off >>= 1) s += __shfl_xor_sync(0xffffffffu, s, off);
    if (lane == 0) d_feats[t * NTAGS + n] = s + bout[n];
}

// -------------------- kernel: Viterbi + backtrace (single CTA) --------------
__global__ void k_viterbi(const float* __restrict__ trans,
                          float* __restrict__ out, int out_size) {
    extern __shared__ float smem[];
    float* sfeat = smem;                                  // TT*NTAGS floats
    unsigned char* sbp = (unsigned char*)(smem + TT * NTAGS);  // TT*NTAGS bytes
    __shared__ float fv[NTAGS];
    __shared__ float fvn[NTAGS];

    int tid = threadIdx.x;
    // stage feats in SMEM (vectorized)
    const float4* d4 = (const float4*)d_feats;
    float4* s4 = (float4*)sfeat;
    for (int i = tid; i < (TT * NTAGS) / 4; i += blockDim.x) s4[i] = d4[i];
    __syncthreads();

    if (tid < 32) {
        int n = tid;
        float tr[NTAGS];
        if (n < NTAGS) {
#pragma unroll
            for (int p = 0; p < NTAGS; p++) tr[p] = trans[n * NTAGS + p];
            fv[n] = (n == START) ? 0.0f : NEGV;
        }
        __syncwarp();
        for (int t = 0; t < TT; t++) {
            if (n < NTAGS) {
                float best = fv[0] + tr[0];
                int bp = 0;
#pragma unroll
                for (int p = 1; p < NTAGS; p++) {
                    float s = fv[p] + tr[p];
                    if (s > best) { best = s; bp = p; }
                }
                fvn[n] = best + sfeat[t * NTAGS + n];
                sbp[t * NTAGS + n] = (unsigned char)bp;
            }
            __syncwarp();
            if (n < NTAGS) fv[n] = fvn[n];
            __syncwarp();
        }
        if (n == 0) {
            float best = fv[0] + trans[STOP * NTAGS + 0];
            int bt = 0;
#pragma unroll
            for (int p = 1; p < NTAGS; p++) {
                float s = fv[p] + trans[STOP * NTAGS + p];
                if (s > best) { best = s; bt = p; }
            }
            if (out_size > 0) out[0] = best;              // path_score
            int tag = bt;
            if (1 + (TT - 1) < out_size) out[1 + (TT - 1)] = (float)tag;
            for (int t = TT - 1; t >= 1; t--) {
                tag = sbp[t * NTAGS + tag];
                if (t < out_size) out[t] = (float)tag;    // out[1 + (t-1)]
            }
        }
    }
}

// -------------------- launcher ----------------------------------------------
extern "C" void kernel_launch(void* const* d_in, const int* in_sizes, int n_in,
                              void* d_out, int out_size) {
    const int*   sent  = (const int*)d_in[0];
    const float* h0    = (const float*)d_in[1];
    const float* c0    = (const float*)d_in[2];
    const float* embed = (const float*)d_in[3];
    const float* Wih_f = (const float*)d_in[4];
    const float* Whh_f = (const float*)d_in[5];
    const float* bih_f = (const float*)d_in[6];
    const float* bhh_f = (const float*)d_in[7];
    const float* Wih_b = (const float*)d_in[8];
    const float* Whh_b = (const float*)d_in[9];
    const float* bih_b = (const float*)d_in[10];
    const float* bhh_b = (const float*)d_in[11];
    const float* Wout  = (const float*)d_in[12];
    const float* bout  = (const float*)d_in[13];
    const float* trans = (const float*)d_in[14];
    float* out = (float*)d_out;

    k_zero<<<32, 256>>>();
    k_gather<<<TT, 256>>>(sent, embed);
    dim3 gg(G4 / 128, TT / 128, 2);
    k_gemm<<<gg, 256>>>(Wih_f, Wih_b, bih_f, bhh_f, bih_b, bhh_b);
    k_recur<<<2 * NCTA, 512>>>(Whh_f, Whh_b, h0, c0);
    k_feats<<<TT, 160>>>(Wout, bout);

    int vit_smem = TT * NTAGS * (int)sizeof(float) + TT * NTAGS;  // 102400 B
    cudaFuncSetAttribute(k_viterbi, cudaFuncAttributeMaxDynamicSharedMemorySize,
                         vit_smem);
    k_viterbi<<<1, 128, vit_smem>>>(trans, out, out_size);
}

// round 2
// speedup vs baseline: 1.2414x; 1.2414x over previous
#include <cuda_runtime.h>

// Problem constants
#define TT    4096
#define EMB   1024
#define H2    512
#define NTAGS 5
#define START 3
#define STOP  4
#define NEGV  -10000.0f

// Recurrence parallelization: 64 CTAs per direction, 8 hidden units each
#define NCTA  64
#define HPER  8

// -------------------- scratch (static device globals; no allocs) ------------
__device__ float d_xs[TT * EMB];          // embedded inputs (16 MB)
__device__ float d_h[2][TT * H2];         // hidden states   (16 MB)
__device__ float d_feats[TT * NTAGS];     // tag scores
__device__ int   d_cnt[2][TT];            // per-step arrival counters

// -------------------- helpers ----------------------------------------------
__device__ __forceinline__ int ld_acq(const int* p) {
    int v;
    asm volatile("ld.acquire.gpu.b32 %0, [%1];" : "=r"(v) : "l"(p) : "memory");
    return v;
}
__device__ __forceinline__ void red_rel(int* p) {
    asm volatile("red.release.gpu.global.add.u32 [%0], 1;" :: "l"(p) : "memory");
}
__device__ __forceinline__ float sigmoidf(float x) {
    return 1.0f / (1.0f + expf(-x));
}

// -------------------- kernel: zero counters ---------------------------------
__global__ void k_zero() {
    int i = blockIdx.x * blockDim.x + threadIdx.x;
    if (i < 2 * TT) d_cnt[i / TT][i % TT] = 0;
}

// -------------------- kernel: embedding gather ------------------------------
__global__ void k_gather(const int* __restrict__ sent,
                         const float* __restrict__ embed) {
    int t = blockIdx.x;
    int row = sent[t];
    const float4* src = (const float4*)(embed + (size_t)row * EMB);
    float4* dst = (float4*)(d_xs + (size_t)t * EMB);
    dst[threadIdx.x] = src[threadIdx.x];   // 256 threads * float4 = 1024 floats
}

// -------------------- fused persistent LSTM (input GEMM + recurrence) -------
// grid = 128 CTAs (64 per direction), 512 threads. CTA owns 8 hidden units =
// 32 gate rows. Each warp owns 2 gate rows. Per thread registers:
//   whh[2][16]  row k-slice of Whh  (k = q*128 + lane*4 + m, q<4)
//   wih[2][32]  row k-slice of Wih  (k = q*128 + lane*4 + m, q<8)
// Per step: GEMV(h) -> activation -> STG h -> red.release -> compute G(t+1)
// slice from x (overlaps the barrier wait) -> acquire-spin -> next step.
__global__ void __launch_bounds__(512, 1) k_recur(
    const float* __restrict__ Whh_f, const float* __restrict__ Whh_b,
    const float* __restrict__ Wih_f, const float* __restrict__ Wih_b,
    const float* __restrict__ bih_f, const float* __restrict__ bhh_f,
    const float* __restrict__ bih_b, const float* __restrict__ bhh_b,
    const float* __restrict__ h0, const float* __restrict__ c0) {
    int dir   = blockIdx.x >> 6;          // / NCTA
    int slice = blockIdx.x & 63;
    int hbase = slice * HPER;
    const float* Whh = dir ? Whh_b : Whh_f;
    const float* Wih = dir ? Wih_b : Wih_f;
    const float* bih = dir ? bih_b : bih_f;
    const float* bhh = dir ? bhh_b : bhh_f;
    float* hout = d_h[dir];
    int* cnt = d_cnt[dir];

    int tid = threadIdx.x;
    int warp = tid >> 5, lane = tid & 31;

    // global gate-row indices for this warp's 2 local rows
    int rows[2];
#pragma unroll
    for (int i = 0; i < 2; i++) {
        int r = 2 * warp + i;             // 0..31
        rows[i] = (r >> 3) * H2 + hbase + (r & 7);
    }

    // load weight slices into registers
    float whh[2][16], wih[2][32];
#pragma unroll
    for (int i = 0; i < 2; i++) {
#pragma unroll
        for (int q = 0; q < 4; q++) {
            float4 v = *(const float4*)(Whh + (size_t)rows[i] * H2 + q * 128 + lane * 4);
            whh[i][q*4+0] = v.x; whh[i][q*4+1] = v.y;
            whh[i][q*4+2] = v.z; whh[i][q*4+3] = v.w;
        }
#pragma unroll
        for (int q = 0; q < 8; q++) {
            float4 v = *(const float4*)(Wih + (size_t)rows[i] * EMB + q * 128 + lane * 4);
            wih[i][q*4+0] = v.x; wih[i][q*4+1] = v.y;
            wih[i][q*4+2] = v.z; wih[i][q*4+3] = v.w;
        }
    }

    __shared__ __align__(16) float sh[H2];
    __shared__ float rec_s[32];
    __shared__ float g_buf[2][32];

    float cj = 0.0f, b0 = 0.0f, b1 = 0.0f, b2 = 0.0f, b3 = 0.0f;
    if (tid < HPER) {
        cj = c0[dir * H2 + hbase + tid];
        b0 = bih[0*H2 + hbase + tid] + bhh[0*H2 + hbase + tid];
        b1 = bih[1*H2 + hbase + tid] + bhh[1*H2 + hbase + tid];
        b2 = bih[2*H2 + hbase + tid] + bhh[2*H2 + hbase + tid];
        b3 = bih[3*H2 + hbase + tid] + bhh[3*H2 + hbase + tid];
    }

    // G(0) slice
    {
        int src = dir ? (TT - 1) : 0;
        const float* x = d_xs + (size_t)src * EMB;
        float a0 = 0.0f, a1 = 0.0f;
#pragma unroll
        for (int q = 0; q < 8; q++) {
            float4 xv = *(const float4*)(x + q * 128 + lane * 4);
            a0 += wih[0][q*4+0]*xv.x + wih[0][q*4+1]*xv.y + wih[0][q*4+2]*xv.z + wih[0][q*4+3]*xv.w;
            a1 += wih[1][q*4+0]*xv.x + wih[1][q*4+1]*xv.y + wih[1][q*4+2]*xv.z + wih[1][q*4+3]*xv.w;
        }
#pragma unroll
        for (int off = 16; off > 0; off >>= 1) {
            a0 += __shfl_xor_sync(0xffffffffu, a0, off);
            a1 += __shfl_xor_sync(0xffffffffu, a1, off);
        }
        if (lane == 0) { g_buf[0][2*warp] = a0; g_buf[0][2*warp+1] = a1; }
    }

    for (int t = 0; t < TT; t++) {
        const float* hp = (t == 0) ? (h0 + dir * H2)
                                   : (hout + (size_t)(t - 1) * H2);
        sh[tid] = hp[tid];
        __syncthreads();                   // sh + g_buf[t&1] ready

        // recurrent GEMV
        float a0 = 0.0f, a1 = 0.0f;
#pragma unroll
        for (int q = 0; q < 4; q++) {
            float4 hv = *(const float4*)(sh + q * 128 + lane * 4);
            a0 += whh[0][q*4+0]*hv.x + whh[0][q*4+1]*hv.y + whh[0][q*4+2]*hv.z + whh[0][q*4+3]*hv.w;
            a1 += whh[1][q*4+0]*hv.x + whh[1][q*4+1]*hv.y + whh[1][q*4+2]*hv.z + whh[1][q*4+3]*hv.w;
        }
#pragma unroll
        for (int off = 16; off > 0; off >>= 1) {
            a0 += __shfl_xor_sync(0xffffffffu, a0, off);
            a1 += __shfl_xor_sync(0xffffffffu, a1, off);
        }
        if (lane == 0) { rec_s[2*warp] = a0; rec_s[2*warp+1] = a1; }
        __syncthreads();                   // rec_s ready

        // activation + h write + release (warp 0 only; on the critical path)
        if (warp == 0) {
            if (lane < HPER) {
                int j = lane, p = t & 1;
                float gi = rec_s[0*HPER + j] + g_buf[p][0*HPER + j] + b0;
                float gf = rec_s[1*HPER + j] + g_buf[p][1*HPER + j] + b1;
                float gg = rec_s[2*HPER + j] + g_buf[p][2*HPER + j] + b2;
                float go = rec_s[3*HPER + j] + g_buf[p][3*HPER + j] + b3;
                cj = sigmoidf(gf) * cj + sigmoidf(gi) * tanhf(gg);
                float hj = sigmoidf(go) * tanhf(cj);
                hout[(size_t)t * H2 + hbase + j] = hj;
            }
            __syncwarp();
            if (lane == 0) red_rel(&cnt[t]);
        }

        // compute G(t+1) slice — overlaps the barrier wait
        if (t + 1 < TT) {
            int src = dir ? (TT - 2 - t) : (t + 1);
            const float* x = d_xs + (size_t)src * EMB;
            float c0a = 0.0f, c1a = 0.0f;
#pragma unroll
            for (int q = 0; q < 8; q++) {
                float4 xv = *(const float4*)(x + q * 128 + lane * 4);
                c0a += wih[0][q*4+0]*xv.x + wih[0][q*4+1]*xv.y + wih[0][q*4+2]*xv.z + wih[0][q*4+3]*xv.w;
                c1a += wih[1][q*4+0]*xv.x + wih[1][q*4+1]*xv.y + wih[1][q*4+2]*xv.z + wih[1][q*4+3]*xv.w;
            }
#pragma unroll
            for (int off = 16; off > 0; off >>= 1) {
                c0a += __shfl_xor_sync(0xffffffffu, c0a, off);
                c1a += __shfl_xor_sync(0xffffffffu, c1a, off);
            }
            if (lane == 0) {
                int p = (t + 1) & 1;
                g_buf[p][2*warp] = c0a; g_buf[p][2*warp+1] = c1a;
            }
        }

        // wait for all 64 CTAs of this direction
        if (tid == 0) {
            while (ld_acq(&cnt[t]) < NCTA) { }
        }
        __syncthreads();
    }
}

// -------------------- kernel: output projection feats = [hf|hb] @ Wout^T ----
__global__ void k_feats(const float* __restrict__ Wout,
                        const float* __restrict__ bout) {
    int t = blockIdx.x;
    int n = threadIdx.x >> 5;              // 5 warps -> 5 tags
    int lane = threadIdx.x & 31;
    const float* hf = d_h[0] + (size_t)t * H2;
    const float* hb = d_h[1] + (size_t)(TT - 1 - t) * H2;
    float s = 0.0f;
    const float* Wn = Wout + (size_t)n * (2 * H2);
#pragma unroll 4
    for (int k = lane; k < H2; k += 32) s += Wn[k] * hf[k];
#pragma unroll 4
    for (int k = lane; k < H2; k += 32) s += Wn[H2 + k] * hb[k];
#pragma unroll
    for (int off = 16; off > 0; off >>= 1) s += __shfl_xor_sync(0xffffffffu, s, off);
    if (lane == 0) d_feats[t * NTAGS + n] = s + bout[n];
}

// -------------------- kernel: Viterbi + backtrace (single CTA) --------------
__global__ void k_viterbi(const float* __restrict__ trans,
                          float* __restrict__ out, int out_size) {
    extern __shared__ float smem[];
    float* sfeat = smem;                                      // TT*NTAGS floats
    unsigned char* sbp = (unsigned char*)(smem + TT * NTAGS); // TT*NTAGS bytes
    __shared__ float fv[NTAGS];
    __shared__ float fvn[NTAGS];

    int tid = threadIdx.x;
    const float4* d4 = (const float4*)d_feats;
    float4* s4 = (float4*)sfeat;
    for (int i = tid; i < (TT * NTAGS) / 4; i += blockDim.x) s4[i] = d4[i];
    __syncthreads();

    if (tid < 32) {
        int n = tid;
        float tr[NTAGS];
        if (n < NTAGS) {
#pragma unroll
            for (int p = 0; p < NTAGS; p++) tr[p] = trans[n * NTAGS + p];
            fv[n] = (n == START) ? 0.0f : NEGV;
        }
        __syncwarp();
        for (int t = 0; t < TT; t++) {
            if (n < NTAGS) {
                float best = fv[0] + tr[0];
                int bp = 0;
#pragma unroll
                for (int p = 1; p < NTAGS; p++) {
                    float s = fv[p] + tr[p];
                    if (s > best) { best = s; bp = p; }
                }
                fvn[n] = best + sfeat[t * NTAGS + n];
                sbp[t * NTAGS + n] = (unsigned char)bp;
            }
            __syncwarp();
            if (n < NTAGS) fv[n] = fvn[n];
            __syncwarp();
        }
        if (n == 0) {
            float best = fv[0] + trans[STOP * NTAGS + 0];
            int bt = 0;
#pragma unroll
            for (int p = 1; p < NTAGS; p++) {
                float s = fv[p] + trans[STOP * NTAGS + p];
                if (s > best) { best = s; bt = p; }
            }
            if (out_size > 0) out[0] = best;
            int tag = bt;
            if (1 + (TT - 1) < out_size) out[1 + (TT - 1)] = (float)tag;
            for (int t = TT - 1; t >= 1; t--) {
                tag = sbp[t * NTAGS + tag];
                if (t < out_size) out[t] = (float)tag;
            }
        }
    }
}

// -------------------- launcher ----------------------------------------------
extern "C" void kernel_launch(void* const* d_in, const int* in_sizes, int n_in,
                              void* d_out, int out_size) {
    const int*   sent  = (const int*)d_in[0];
    const float* h0    = (const float*)d_in[1];
    const float* c0    = (const float*)d_in[2];
    const float* embed = (const float*)d_in[3];
    const float* Wih_f = (const float*)d_in[4];
    const float* Whh_f = (const float*)d_in[5];
    const float* bih_f = (const float*)d_in[6];
    const float* bhh_f = (const float*)d_in[7];
    const float* Wih_b = (const float*)d_in[8];
    const float* Whh_b = (const float*)d_in[9];
    const float* bih_b = (const float*)d_in[10];
    const float* bhh_b = (const float*)d_in[11];
    const float* Wout  = (const float*)d_in[12];
    const float* bout  = (const float*)d_in[13];
    const float* trans = (const float*)d_in[14];
    float* out = (float*)d_out;

    k_zero<<<32, 256>>>();
    k_gather<<<TT, 256>>>(sent, embed);
    k_recur<<<2 * NCTA, 512>>>(Whh_f, Whh_b, Wih_f, Wih_b,
                               bih_f, bhh_f, bih_b, bhh_b, h0, c0);
    k_feats<<<TT, 160>>>(Wout, bout);

    int vit_smem = TT * NTAGS * (int)sizeof(float) + TT * NTAGS;  // 102400 B
    cudaFuncSetAttribute(k_viterbi, cudaFuncAttributeMaxDynamicSharedMemorySize,
                         vit_smem);
    k_viterbi<<<1, 128, vit_smem>>>(trans, out, out_size);
}